// round 15
// baseline (speedup 1.0000x reference)
#include <cuda_runtime.h>
#include <cuda_fp16.h>
#include <cstdint>

#define NT 256

// ---------------- global scratch (no runtime allocation allowed) ----------------
static __device__ float   g_seg[(size_t)50176 * 128];   // scatter-sum (fp32 atomics)
static __device__ __half  g_h0s[(size_t)50176 * 128];   // nodeF @ eW0(sender), fp16
static __device__ __half  g_h0r[(size_t)50176 * 128];   // nodeF @ eW0(receiver), fp16
static __device__ __half  g_h0n[(size_t)50176 * 128];   // nodeF @ nW0(node part), fp16
static __device__ __half  g_wh[9 * 16384];              // weights (fp16), fragment-major

// ---------------- helpers ----------------
__device__ __forceinline__ uint32_t cvt2(float2 v) {
    __half2 h = __floats2half2_rn(v.x, v.y);
    return *reinterpret_cast<const uint32_t*>(&h);
}
__device__ __forceinline__ uint32_t cvt2f(float x, float y) {
    return cvt2(make_float2(x, y));
}
__device__ __forceinline__ float2 h2f(uint32_t u) {
    __half2 h = *reinterpret_cast<const __half2*>(&u);
    return __half22float2(h);
}
// m16n8k16 fp16 MMA, fp32 accumulate (baseline PTX, valid on sm_103).
__device__ __forceinline__ void mma4(float* c, const uint32_t* a, uint2 b) {
    asm("mma.sync.aligned.m16n8k16.row.col.f32.f16.f16.f32 "
        "{%0,%1,%2,%3}, {%4,%5,%6,%7}, {%8,%9}, {%0,%1,%2,%3};"
        : "+f"(c[0]), "+f"(c[1]), "+f"(c[2]), "+f"(c[3])
        : "r"(a[0]), "r"(a[1]), "r"(a[2]), "r"(a[3]), "r"(b.x), "r"(b.y));
}
// One K=16 step, 32 rows: each B fragment loaded ONCE, used by TWO MMAs.
__device__ __forceinline__ void mma_step2(float* acc, const uint32_t* a0,
                                          const uint32_t* a1, const char* bbase) {
    #pragma unroll
    for (int t = 0; t < 16; ++t) {
        uint2 wh = *(const uint2*)(bbase + t * 256);
        mma4(&acc[t * 8], a0, wh);
        mma4(&acc[t * 8 + 4], a1, wh);
    }
}
// 16-row variant (precomp only)
__device__ __forceinline__ void mma_step(float* acc, const uint32_t* ah, const char* bbase) {
    #pragma unroll
    for (int t = 0; t < 16; ++t) {
        uint2 wh = *(const uint2*)(bbase + t * 256);
        mma4(&acc[t * 4], ah, wh);
    }
}

// ---------------- async copy of one 32KB weight image ----------------
__device__ __forceinline__ void cp_img(void* smem_dst, int img, int tid) {
    uint32_t d = (uint32_t)__cvta_generic_to_shared(smem_dst);
    const uint4* src = (const uint4*)(g_wh + (size_t)img * 16384);
    #pragma unroll
    for (int i = tid; i < 2048; i += NT)
        asm volatile("cp.async.ca.shared.global [%0], [%1], 16;"
                     :: "r"(d + i * 16), "l"(src + i));
    asm volatile("cp.async.commit_group;" ::: "memory");
}
__device__ __forceinline__ void cp_wait_all() {
    asm volatile("cp.async.wait_group 0;" ::: "memory");
}

// ---------------- prep kernels ----------------
__global__ void zero_seg_kernel(int n4) {
    int i = blockIdx.x * blockDim.x + threadIdx.x;
    if (i < n4) reinterpret_cast<float4*>(g_seg)[i] = make_float4(0.f, 0.f, 0.f, 0.f);
}
// images: 0..2=eW0 chunks, 3=eW1, 4=eW2, 5..6=nW0 chunks, 7=nW1, 8=nW2
__global__ void prep_all_kernel(const float* __restrict__ eW0, const float* __restrict__ eW1,
                                const float* __restrict__ eW2, const float* __restrict__ nW0,
                                const float* __restrict__ nW1, const float* __restrict__ nW2) {
    int t = blockIdx.x * blockDim.x + threadIdx.x;
    if (t >= 1152 * 128) return;
    int kg = t >> 7, n = t & 127;
    const float* W; int k, baseImg;
    if      (kg < 384)  { W = eW0; k = kg;        baseImg = 0; }
    else if (kg < 512)  { W = eW1; k = kg - 384;  baseImg = 3; }
    else if (kg < 640)  { W = eW2; k = kg - 512;  baseImg = 4; }
    else if (kg < 896)  { W = nW0; k = kg - 640;  baseImg = 5; }
    else if (kg < 1024) { W = nW1; k = kg - 896;  baseImg = 7; }
    else                { W = nW2; k = kg - 1024; baseImg = 8; }
    float x = W[k * 128 + n];
    int chunk = k >> 7, kc = k & 127;
    int kstep = kc >> 4, kk = kc & 15;
    int reg = kk >> 3, kb = kk & 7;
    int lane = (n & 7) * 4 + (kb >> 1), cb = kb & 1;
    int frag = kstep * 16 + (n >> 3);
    size_t di = (size_t)(baseImg + chunk) * 16384 + (size_t)frag * 128 + lane * 4 + reg * 2 + cb;
    g_wh[di] = __float2half_rn(x);
}

// ---------------- SMEM maps (bytes) ----------------
#define SM_BUF0 0
#define SM_BUF1 32768
#define SM_B0   65536
#define SM_B1   66048
#define SM_B2   66560
#define SM_G    67072
#define SM_BE   67584
#define SMEM_TOTAL 68096
#define SMEM_PRE   32768

// ---------------- precompute: H0s/H0r/H0n (fp16 out) ----------------
__global__ __launch_bounds__(NT, 2)
void precomp_kernel(const float* __restrict__ nodef, int Nn, int ntiles,
                    int i0, int i1, int i2)
{
    extern __shared__ char smem[];
    const int tid = threadIdx.x, wid = tid >> 5, lane = tid & 31, q = lane & 3;
    const int rl = wid * 16 + (lane >> 2);
    const int imgs[3] = {i0, i1, i2};
    __half* const outs[3] = {g_h0s, g_h0r, g_h0n};

    for (int j = 0; j < 3; ++j) {
        __syncthreads();
        cp_img(smem, imgs[j], tid);
        cp_wait_all();
        __syncthreads();
        for (int tile = blockIdx.x; tile < ntiles; tile += gridDim.x) {
            const int gel = tile * 128 + rl, geh = gel + 8;
            const int gl = min(gel, Nn - 1), gh = min(geh, Nn - 1);
            const float* pl = nodef + (size_t)gl * 128;
            const float* ph = nodef + (size_t)gh * 128;
            float acc[64];
            #pragma unroll
            for (int i = 0; i < 64; ++i) acc[i] = 0.f;
            #pragma unroll
            for (int s = 0; s < 8; ++s) {
                const int k0 = s * 16 + q * 2;
                uint32_t ahf[4];
                ahf[0] = cvt2(*(const float2*)(pl + k0));
                ahf[1] = cvt2(*(const float2*)(ph + k0));
                ahf[2] = cvt2(*(const float2*)(pl + k0 + 8));
                ahf[3] = cvt2(*(const float2*)(ph + k0 + 8));
                mma_step(acc, ahf, smem + (s * 16) * 256 + (lane << 3));
            }
            __half* o = outs[j];
            #pragma unroll
            for (int t = 0; t < 16; ++t) {
                const int col = t * 8 + q * 2;
                if (gel < Nn)
                    *(uint32_t*)(o + (size_t)gel * 128 + col) = cvt2f(acc[t * 4 + 0], acc[t * 4 + 1]);
                if (geh < Nn)
                    *(uint32_t*)(o + (size_t)geh * 128 + col) = cvt2f(acc[t * 4 + 2], acc[t * 4 + 3]);
            }
        }
    }
}

// ---------------- fused 3-layer MLP + LN + residual (+scatter) ----------------
// One block = one 256-row tile; warp owns 32 rows (2 m16 groups share every B load).
template<bool IS_EDGE>
__global__ __launch_bounds__(NT, 1)
void gnn4(const float* __restrict__ chunkA_in,   // edge: edgef; node: (g_seg used)
          const int*   __restrict__ senders,
          const int*   __restrict__ receivers,
          const float* __restrict__ b0, const float* __restrict__ b1,
          const float* __restrict__ b2,
          const float* __restrict__ gma, const float* __restrict__ bta,
          const float* __restrict__ resid,
          float* __restrict__ out, int M, int wimg0)
{
    extern __shared__ char smem[];
    const int tid = threadIdx.x, wid = tid >> 5, lane = tid & 31, q = lane & 3;
    const int rl = wid * 32 + (lane >> 2);
    const int r0 = blockIdx.x * 256;

    cp_img(smem + SM_BUF0, wimg0, tid);
    for (int i = tid; i < 128; i += NT) {
        ((float*)(smem + SM_B0))[i] = b0[i];
        ((float*)(smem + SM_B1))[i] = b1[i];
        ((float*)(smem + SM_B2))[i] = b2[i];
        ((float*)(smem + SM_G ))[i] = gma[i];
        ((float*)(smem + SM_BE))[i] = bta[i];
    }

    int ge[4], gc[4];
    #pragma unroll
    for (int r = 0; r < 4; ++r) { ge[r] = r0 + rl + 8 * r; gc[r] = min(ge[r], M - 1); }

    float acc[128];

    // ---- acc init from precomputed layer-0 partials (fp16 tables) ----
    if (IS_EDGE) {
        const __half* sp[4]; const __half* rp[4];
        #pragma unroll
        for (int r = 0; r < 4; ++r) {
            sp[r] = g_h0s + (size_t)senders[gc[r]]   * 128;
            rp[r] = g_h0r + (size_t)receivers[gc[r]] * 128;
        }
        #pragma unroll
        for (int t = 0; t < 16; ++t) {
            const int col = t * 8 + q * 2;
            #pragma unroll
            for (int r = 0; r < 4; ++r) {
                float2 a = h2f(*(const uint32_t*)(sp[r] + col));
                float2 b = h2f(*(const uint32_t*)(rp[r] + col));
                acc[t * 8 + r * 2 + 0] = a.x + b.x;
                acc[t * 8 + r * 2 + 1] = a.y + b.y;
            }
        }
    } else {
        #pragma unroll
        for (int t = 0; t < 16; ++t) {
            const int col = t * 8 + q * 2;
            #pragma unroll
            for (int r = 0; r < 4; ++r) {
                float2 a = h2f(*(const uint32_t*)(g_h0n + (size_t)gc[r] * 128 + col));
                acc[t * 8 + r * 2 + 0] = a.x;
                acc[t * 8 + r * 2 + 1] = a.y;
            }
        }
    }

    cp_wait_all();
    __syncthreads();                          // buf0 ready
    cp_img(smem + SM_BUF1, wimg0 + 1, tid);   // prefetch L1 image during L0 MMA

    // ---- layer 0: one K=128 chunk (edgef / seg-sum fp32), B in buf0 ----
    {
        const float* chunkA = IS_EDGE ? chunkA_in : g_seg;
        const float* p0 = chunkA + (size_t)gc[0] * 128;
        const float* p1 = chunkA + (size_t)gc[1] * 128;
        const float* p2 = chunkA + (size_t)gc[2] * 128;
        const float* p3 = chunkA + (size_t)gc[3] * 128;
        #pragma unroll
        for (int s = 0; s < 8; ++s) {
            const int k0 = s * 16 + q * 2;
            uint32_t a0[4], a1[4];
            a0[0] = cvt2(*(const float2*)(p0 + k0));
            a0[1] = cvt2(*(const float2*)(p1 + k0));
            a0[2] = cvt2(*(const float2*)(p0 + k0 + 8));
            a0[3] = cvt2(*(const float2*)(p1 + k0 + 8));
            a1[0] = cvt2(*(const float2*)(p2 + k0));
            a1[1] = cvt2(*(const float2*)(p3 + k0));
            a1[2] = cvt2(*(const float2*)(p2 + k0 + 8));
            a1[3] = cvt2(*(const float2*)(p3 + k0 + 8));
            mma_step2(acc, a0, a1, smem + SM_BUF0 + s * 4096 + (lane << 3));
        }
    }

    // ---- layers 1, 2 ----
    uint32_t Ahi[64];
    #pragma unroll
    for (int L = 1; L <= 2; ++L) {
        const float* bias = (const float*)(smem + (L == 1 ? SM_B0 : SM_B1));
        #pragma unroll
        for (int s = 0; s < 8; ++s) {
            float2 bz0 = *(const float2*)(bias + s * 16 + q * 2);
            float2 bz1 = *(const float2*)(bias + s * 16 + 8 + q * 2);
            const int b_ = 16 * s;
            Ahi[s * 8 + 0] = cvt2f(fmaxf(acc[b_ + 0] + bz0.x, 0.f),  fmaxf(acc[b_ + 1] + bz0.y, 0.f));
            Ahi[s * 8 + 1] = cvt2f(fmaxf(acc[b_ + 2] + bz0.x, 0.f),  fmaxf(acc[b_ + 3] + bz0.y, 0.f));
            Ahi[s * 8 + 2] = cvt2f(fmaxf(acc[b_ + 8] + bz1.x, 0.f),  fmaxf(acc[b_ + 9] + bz1.y, 0.f));
            Ahi[s * 8 + 3] = cvt2f(fmaxf(acc[b_ + 10] + bz1.x, 0.f), fmaxf(acc[b_ + 11] + bz1.y, 0.f));
            Ahi[s * 8 + 4] = cvt2f(fmaxf(acc[b_ + 4] + bz0.x, 0.f),  fmaxf(acc[b_ + 5] + bz0.y, 0.f));
            Ahi[s * 8 + 5] = cvt2f(fmaxf(acc[b_ + 6] + bz0.x, 0.f),  fmaxf(acc[b_ + 7] + bz0.y, 0.f));
            Ahi[s * 8 + 6] = cvt2f(fmaxf(acc[b_ + 12] + bz1.x, 0.f), fmaxf(acc[b_ + 13] + bz1.y, 0.f));
            Ahi[s * 8 + 7] = cvt2f(fmaxf(acc[b_ + 14] + bz1.x, 0.f), fmaxf(acc[b_ + 15] + bz1.y, 0.f));
        }
        cp_wait_all();                 // this layer's image landed
        __syncthreads();               // everyone done with the old buffer
        if (L == 1)                    // prefetch L2 image into buf0 during L1 MMA
            cp_img(smem + SM_BUF0, wimg0 + 2, tid);
        #pragma unroll
        for (int j = 0; j < 128; ++j) acc[j] = 0.f;
        const char* bb = smem + (L == 1 ? SM_BUF1 : SM_BUF0);
        #pragma unroll
        for (int s = 0; s < 8; ++s)
            mma_step2(acc, &Ahi[s * 8], &Ahi[s * 8 + 4], bb + s * 4096 + (lane << 3));
    }

    // ---- final: bias + LayerNorm (4 rows/thread) + residual (+ scatter) ----
    {
        const float* bias = (const float*)(smem + SM_B2);
        float sm_[4] = {0.f, 0.f, 0.f, 0.f}, sq[4] = {0.f, 0.f, 0.f, 0.f};
        #pragma unroll
        for (int t = 0; t < 16; ++t) {
            float2 bz = *(const float2*)(bias + t * 8 + q * 2);
            #pragma unroll
            for (int r = 0; r < 4; ++r) {
                float v0 = acc[t * 8 + r * 2 + 0] + bz.x;
                float v1 = acc[t * 8 + r * 2 + 1] + bz.y;
                acc[t * 8 + r * 2 + 0] = v0; acc[t * 8 + r * 2 + 1] = v1;
                sm_[r] += v0 + v1;
                sq[r] = fmaf(v0, v0, fmaf(v1, v1, sq[r]));
            }
        }
        #pragma unroll
        for (int o = 1; o <= 2; o <<= 1) {
            #pragma unroll
            for (int r = 0; r < 4; ++r) {
                sm_[r] += __shfl_xor_sync(0xffffffffu, sm_[r], o);
                sq[r]  += __shfl_xor_sync(0xffffffffu, sq[r],  o);
            }
        }
        float mu[4], rstd[4];
        #pragma unroll
        for (int r = 0; r < 4; ++r) {
            mu[r] = sm_[r] * (1.f / 128.f);
            rstd[r] = rsqrtf(sq[r] * (1.f / 128.f) - mu[r] * mu[r] + 1e-5f);
        }
        int rv[4];
        if (IS_EDGE) {
            #pragma unroll
            for (int r = 0; r < 4; ++r) rv[r] = receivers[gc[r]];
        }
        const float* gw = (const float*)(smem + SM_G);
        const float* bw = (const float*)(smem + SM_BE);

        #pragma unroll
        for (int t = 0; t < 16; ++t) {
            const int col = t * 8 + q * 2;
            float2 gg = *(const float2*)(gw + col);
            float2 bb = *(const float2*)(bw + col);
            #pragma unroll
            for (int r = 0; r < 4; ++r) {
                if (ge[r] < M) {
                    float ne0 = fmaf(gg.x, (acc[t * 8 + r * 2 + 0] - mu[r]) * rstd[r], bb.x);
                    float ne1 = fmaf(gg.y, (acc[t * 8 + r * 2 + 1] - mu[r]) * rstd[r], bb.y);
                    float2 rf = *(const float2*)(resid + (size_t)ge[r] * 128 + col);
                    *(float2*)(out + (size_t)ge[r] * 128 + col) = make_float2(ne0 + rf.x, ne1 + rf.y);
                    if (IS_EDGE)
                        atomicAdd((float2*)&g_seg[(size_t)rv[r] * 128 + col], make_float2(ne0, ne1));
                }
            }
        }
    }
}

// ---------------- launch ----------------
extern "C" void kernel_launch(void* const* d_in, const int* in_sizes, int n_in,
                              void* d_out, int out_size)
{
    const float* nodef     = (const float*)d_in[0];
    const float* edgef     = (const float*)d_in[1];
    const int*   senders   = (const int*)d_in[2];
    const int*   receivers = (const int*)d_in[3];
    const float* eW0 = (const float*)d_in[4];  const float* eb0 = (const float*)d_in[5];
    const float* eW1 = (const float*)d_in[6];  const float* eb1 = (const float*)d_in[7];
    const float* eW2 = (const float*)d_in[8];  const float* eb2 = (const float*)d_in[9];
    const float* eg  = (const float*)d_in[10]; const float* ebt = (const float*)d_in[11];
    const float* nW0 = (const float*)d_in[12]; const float* nb0 = (const float*)d_in[13];
    const float* nW1 = (const float*)d_in[14]; const float* nb1 = (const float*)d_in[15];
    const float* nW2 = (const float*)d_in[16]; const float* nb2 = (const float*)d_in[17];
    const float* ng  = (const float*)d_in[18]; const float* nbt = (const float*)d_in[19];

    const int N = in_sizes[0] / 128;
    const int E = in_sizes[2];
    float* out_node = (float*)d_out;
    float* out_edge = out_node + (size_t)N * 128;

    cudaFuncSetAttribute(precomp_kernel,
                         cudaFuncAttributeMaxDynamicSharedMemorySize, SMEM_PRE);
    cudaFuncSetAttribute(gnn4<true>,
                         cudaFuncAttributeMaxDynamicSharedMemorySize, SMEM_TOTAL);
    cudaFuncSetAttribute(gnn4<false>,
                         cudaFuncAttributeMaxDynamicSharedMemorySize, SMEM_TOTAL);

    // weight images: 0=eW0s 1=eW0r 2=eW0e 3=eW1 4=eW2 5=nW0a 6=nW0b 7=nW1 8=nW2
    prep_all_kernel<<<(1152 * 128 + 255) / 256, 256>>>(eW0, eW1, eW2, nW0, nW1, nW2);
    zero_seg_kernel<<<(N * 32 + 255) / 256, 256>>>(N * 32);

    const int ntile_n = (N + 127) / 128;

    // H0s / H0r / H0n precompute over nodes (fp16 outputs)
    precomp_kernel<<<296, NT, SMEM_PRE>>>(nodef, N, ntile_n, 0, 1, 5);

    // edge pass (256-row tiles)
    gnn4<true><<<(E + 255) / 256, NT, SMEM_TOTAL>>>(
        edgef, senders, receivers,
        eb0, eb1, eb2, eg, ebt, edgef, out_edge, E, 2);

    // node pass (256-row tiles)
    gnn4<false><<<(N + 255) / 256, NT, SMEM_TOTAL>>>(
        nullptr, nullptr, nullptr,
        nb0, nb1, nb2, ng, nbt, nodef, out_node, N, 6);
}

// round 16
// speedup vs baseline: 1.0858x; 1.0858x over previous
#include <cuda_runtime.h>
#include <cuda_fp16.h>
#include <cstdint>

#define NT 256

// ---------------- global scratch (no runtime allocation allowed) ----------------
static __device__ float   g_seg[(size_t)50176 * 128];   // scatter-sum (fp32 atomics)
static __device__ __half  g_h0s[(size_t)50176 * 128];   // nodeF @ eW0(sender), fp16
static __device__ __half  g_h0r[(size_t)50176 * 128];   // nodeF @ eW0(receiver), fp16
static __device__ __half  g_h0n[(size_t)50176 * 128];   // nodeF @ nW0(node part), fp16
static __device__ __half  g_wh[9 * 16384];              // weights (fp16), fragment-major

// ---------------- helpers ----------------
__device__ __forceinline__ uint32_t cvt2(float2 v) {
    __half2 h = __floats2half2_rn(v.x, v.y);
    return *reinterpret_cast<const uint32_t*>(&h);
}
__device__ __forceinline__ uint32_t cvt2f(float x, float y) {
    return cvt2(make_float2(x, y));
}
__device__ __forceinline__ float2 h2f(uint32_t u) {
    __half2 h = *reinterpret_cast<const __half2*>(&u);
    return __half22float2(h);
}
// m16n8k16 fp16 MMA, fp32 accumulate (baseline PTX, valid on sm_103).
__device__ __forceinline__ void mma4(float* c, const uint32_t* a, uint2 b) {
    asm("mma.sync.aligned.m16n8k16.row.col.f32.f16.f16.f32 "
        "{%0,%1,%2,%3}, {%4,%5,%6,%7}, {%8,%9}, {%0,%1,%2,%3};"
        : "+f"(c[0]), "+f"(c[1]), "+f"(c[2]), "+f"(c[3])
        : "r"(a[0]), "r"(a[1]), "r"(a[2]), "r"(a[3]), "r"(b.x), "r"(b.y));
}
// One K=16 step: 1 LDS.64 + 1 MMA per n-tile.
__device__ __forceinline__ void mma_step(float* acc, const uint32_t* ah, const char* bbase) {
    #pragma unroll
    for (int t = 0; t < 16; ++t) {
        uint2 wh = *(const uint2*)(bbase + t * 256);
        mma4(&acc[t * 4], ah, wh);
    }
}

// ---------------- async copy of one 32KB weight image ----------------
__device__ __forceinline__ void cp_img(void* smem_dst, int img, int tid) {
    uint32_t d = (uint32_t)__cvta_generic_to_shared(smem_dst);
    const uint4* src = (const uint4*)(g_wh + (size_t)img * 16384);
    #pragma unroll
    for (int i = tid; i < 2048; i += NT)
        asm volatile("cp.async.ca.shared.global [%0], [%1], 16;"
                     :: "r"(d + i * 16), "l"(src + i));
    asm volatile("cp.async.commit_group;" ::: "memory");
}
__device__ __forceinline__ void cp_wait_all() {
    asm volatile("cp.async.wait_group 0;" ::: "memory");
}

// ---------------- coalesced per-warp staging (16 rows x 128 cols fp16) ----------------
// stage layout: 16 rows, stride 68 uint32 (272B) -> bank index (4*row + q), conflict-free.
// uint32 index j in a row holds cols 2j, 2j+1.
__device__ __forceinline__ void stage_h0_edge(uint32_t* stg, const int* idx0, const int* idx1,
                                              int rowbase, int M, int lane) {
    #pragma unroll 4
    for (int lr = 0; lr < 16; ++lr) {
        int rc = min(rowbase + lr, M - 1);
        const uint32_t* ps = (const uint32_t*)(g_h0s + (size_t)idx0[rc] * 128);
        const uint32_t* pr = (const uint32_t*)(g_h0r + (size_t)idx1[rc] * 128);
        uint2 va = *(const uint2*)(ps + lane * 2);
        uint2 vb = *(const uint2*)(pr + lane * 2);
        __half2 s0 = __hadd2(*(__half2*)&va.x, *(__half2*)&vb.x);
        __half2 s1 = __hadd2(*(__half2*)&va.y, *(__half2*)&vb.y);
        stg[lr * 68 + lane * 2]     = *(uint32_t*)&s0;
        stg[lr * 68 + lane * 2 + 1] = *(uint32_t*)&s1;
    }
}
__device__ __forceinline__ void stage_h0_node(uint32_t* stg, int rowbase, int Nn, int lane) {
    #pragma unroll 4
    for (int lr = 0; lr < 16; ++lr) {
        int rc = min(rowbase + lr, Nn - 1);
        const uint32_t* p = (const uint32_t*)(g_h0n + (size_t)rc * 128);
        uint2 v = *(const uint2*)(p + lane * 2);
        stg[lr * 68 + lane * 2]     = v.x;
        stg[lr * 68 + lane * 2 + 1] = v.y;
    }
}
__device__ __forceinline__ void stage_f32(uint32_t* stg, const float* src,
                                          int rowbase, int M, int lane) {
    #pragma unroll 4
    for (int lr = 0; lr < 16; ++lr) {
        int rc = min(rowbase + lr, M - 1);
        const float2* p = (const float2*)(src + (size_t)rc * 128);
        stg[lr * 68 + lane]      = cvt2(p[lane]);
        stg[lr * 68 + lane + 32] = cvt2(p[lane + 32]);
    }
}

// ---------------- prep kernels ----------------
__global__ void zero_seg_kernel(int n4) {
    int i = blockIdx.x * blockDim.x + threadIdx.x;
    if (i < n4) reinterpret_cast<float4*>(g_seg)[i] = make_float4(0.f, 0.f, 0.f, 0.f);
}
// images: 0..2=eW0 chunks, 3=eW1, 4=eW2, 5..6=nW0 chunks, 7=nW1, 8=nW2
__global__ void prep_all_kernel(const float* __restrict__ eW0, const float* __restrict__ eW1,
                                const float* __restrict__ eW2, const float* __restrict__ nW0,
                                const float* __restrict__ nW1, const float* __restrict__ nW2) {
    int t = blockIdx.x * blockDim.x + threadIdx.x;
    if (t >= 1152 * 128) return;
    int kg = t >> 7, n = t & 127;
    const float* W; int k, baseImg;
    if      (kg < 384)  { W = eW0; k = kg;        baseImg = 0; }
    else if (kg < 512)  { W = eW1; k = kg - 384;  baseImg = 3; }
    else if (kg < 640)  { W = eW2; k = kg - 512;  baseImg = 4; }
    else if (kg < 896)  { W = nW0; k = kg - 640;  baseImg = 5; }
    else if (kg < 1024) { W = nW1; k = kg - 896;  baseImg = 7; }
    else                { W = nW2; k = kg - 1024; baseImg = 8; }
    float x = W[k * 128 + n];
    int chunk = k >> 7, kc = k & 127;
    int kstep = kc >> 4, kk = kc & 15;
    int reg = kk >> 3, kb = kk & 7;
    int lane = (n & 7) * 4 + (kb >> 1), cb = kb & 1;
    int frag = kstep * 16 + (n >> 3);
    size_t di = (size_t)(baseImg + chunk) * 16384 + (size_t)frag * 128 + lane * 4 + reg * 2 + cb;
    g_wh[di] = __float2half_rn(x);
}

// ---------------- SMEM maps (bytes) ----------------
#define SM_BUF0 0
#define SM_BUF1 32768
#define SM_STG  65536            // 8 warps x 4352 B (16 rows x 272 B)
#define SM_B0   100352
#define SM_B1   100864
#define SM_B2   101376
#define SM_G    101888
#define SM_BE   102400
#define SMEM_TOTAL 102912
#define SMEM_PRE   32768

// ---------------- precompute: H0s/H0r/H0n (fp16 out) ----------------
__global__ __launch_bounds__(NT, 2)
void precomp_kernel(const float* __restrict__ nodef, int Nn, int ntiles,
                    int i0, int i1, int i2)
{
    extern __shared__ char smem[];
    const int tid = threadIdx.x, wid = tid >> 5, lane = tid & 31, q = lane & 3;
    const int rl = wid * 16 + (lane >> 2);
    const int imgs[3] = {i0, i1, i2};
    __half* const outs[3] = {g_h0s, g_h0r, g_h0n};

    for (int j = 0; j < 3; ++j) {
        __syncthreads();
        cp_img(smem, imgs[j], tid);
        cp_wait_all();
        __syncthreads();
        for (int tile = blockIdx.x; tile < ntiles; tile += gridDim.x) {
            const int gel = tile * 128 + rl, geh = gel + 8;
            const int gl = min(gel, Nn - 1), gh = min(geh, Nn - 1);
            const float* pl = nodef + (size_t)gl * 128;
            const float* ph = nodef + (size_t)gh * 128;
            float acc[64];
            #pragma unroll
            for (int i = 0; i < 64; ++i) acc[i] = 0.f;
            #pragma unroll
            for (int s = 0; s < 8; ++s) {
                const int k0 = s * 16 + q * 2;
                uint32_t ahf[4];
                ahf[0] = cvt2(*(const float2*)(pl + k0));
                ahf[1] = cvt2(*(const float2*)(ph + k0));
                ahf[2] = cvt2(*(const float2*)(pl + k0 + 8));
                ahf[3] = cvt2(*(const float2*)(ph + k0 + 8));
                mma_step(acc, ahf, smem + (s * 16) * 256 + (lane << 3));
            }
            __half* o = outs[j];
            #pragma unroll
            for (int t = 0; t < 16; ++t) {
                const int col = t * 8 + q * 2;
                if (gel < Nn)
                    *(uint32_t*)(o + (size_t)gel * 128 + col) = cvt2f(acc[t * 4 + 0], acc[t * 4 + 1]);
                if (geh < Nn)
                    *(uint32_t*)(o + (size_t)geh * 128 + col) = cvt2f(acc[t * 4 + 2], acc[t * 4 + 3]);
            }
        }
    }
}

// ---------------- fused 3-layer MLP + LN + residual (+scatter) ----------------
// R14 core (16-row warps, 2 blk/SM, cp.async dbuf) + coalesced per-warp staging.
template<bool IS_EDGE>
__global__ __launch_bounds__(NT, 2)
void gnn5(const float* __restrict__ chunkA_in,   // edge: edgef; node: (g_seg used)
          const int*   __restrict__ senders,
          const int*   __restrict__ receivers,
          const float* __restrict__ b0, const float* __restrict__ b1,
          const float* __restrict__ b2,
          const float* __restrict__ gma, const float* __restrict__ bta,
          const float* __restrict__ resid,
          float* __restrict__ out, int M, int wimg0)
{
    extern __shared__ char smem[];
    const int tid = threadIdx.x, wid = tid >> 5, lane = tid & 31, q = lane & 3;
    const int rl = wid * 16 + (lane >> 2);
    const int r0 = blockIdx.x * 128;
    const int rowbase = r0 + wid * 16;

    // prologue: start img0 copy async, then stage params (overlap)
    cp_img(smem + SM_BUF0, wimg0, tid);
    for (int i = tid; i < 128; i += NT) {
        ((float*)(smem + SM_B0))[i] = b0[i];
        ((float*)(smem + SM_B1))[i] = b1[i];
        ((float*)(smem + SM_B2))[i] = b2[i];
        ((float*)(smem + SM_G ))[i] = gma[i];
        ((float*)(smem + SM_BE))[i] = bta[i];
    }

    uint32_t* stg = (uint32_t*)(smem + SM_STG) + wid * 1088;
    const int gel = r0 + rl, geh = gel + 8;
    const int gl = min(gel, M - 1), gh = min(geh, M - 1);

    // ---- stage layer-0 partials coalesced, then read fragments ----
    if (IS_EDGE) stage_h0_edge(stg, senders, receivers, rowbase, M, lane);
    else         stage_h0_node(stg, rowbase, M, lane);
    __syncwarp();

    float acc[64];
    #pragma unroll
    for (int t = 0; t < 16; ++t) {
        float2 a = h2f(stg[(lane >> 2) * 68 + t * 4 + q]);
        float2 b = h2f(stg[((lane >> 2) + 8) * 68 + t * 4 + q]);
        acc[t * 4 + 0] = a.x; acc[t * 4 + 1] = a.y;
        acc[t * 4 + 2] = b.x; acc[t * 4 + 3] = b.y;
    }
    __syncwarp();

    // ---- stage L0 A source (edgef / seg-sum) coalesced ----
    stage_f32(stg, IS_EDGE ? chunkA_in : g_seg, rowbase, M, lane);

    cp_wait_all();
    __syncthreads();                          // buf0 ready (also orders stg reads)
    cp_img(smem + SM_BUF1, wimg0 + 1, tid);   // prefetch L1 image during L0 MMA

    // ---- layer 0: fragments from staged SMEM, B in buf0 ----
    #pragma unroll
    for (int s = 0; s < 8; ++s) {
        uint32_t ahf[4];
        ahf[0] = stg[(lane >> 2) * 68 + s * 8 + q];
        ahf[1] = stg[((lane >> 2) + 8) * 68 + s * 8 + q];
        ahf[2] = stg[(lane >> 2) * 68 + s * 8 + 4 + q];
        ahf[3] = stg[((lane >> 2) + 8) * 68 + s * 8 + 4 + q];
        mma_step(acc, ahf, smem + SM_BUF0 + (s * 16) * 256 + (lane << 3));
    }

    // ---- layers 1, 2 ----
    uint32_t Ahi[32];
    #pragma unroll
    for (int L = 1; L <= 2; ++L) {
        const float* bias = (const float*)(smem + (L == 1 ? SM_B0 : SM_B1));
        #pragma unroll
        for (int s = 0; s < 8; ++s) {
            const int t0 = 2 * s, t1 = 2 * s + 1;
            float2 bz0 = *(const float2*)(bias + t0 * 8 + q * 2);
            float2 bz1 = *(const float2*)(bias + t1 * 8 + q * 2);
            Ahi[s * 4 + 0] = cvt2f(fmaxf(acc[t0 * 4 + 0] + bz0.x, 0.f),
                                   fmaxf(acc[t0 * 4 + 1] + bz0.y, 0.f));
            Ahi[s * 4 + 1] = cvt2f(fmaxf(acc[t0 * 4 + 2] + bz0.x, 0.f),
                                   fmaxf(acc[t0 * 4 + 3] + bz0.y, 0.f));
            Ahi[s * 4 + 2] = cvt2f(fmaxf(acc[t1 * 4 + 0] + bz1.x, 0.f),
                                   fmaxf(acc[t1 * 4 + 1] + bz1.y, 0.f));
            Ahi[s * 4 + 3] = cvt2f(fmaxf(acc[t1 * 4 + 2] + bz1.x, 0.f),
                                   fmaxf(acc[t1 * 4 + 3] + bz1.y, 0.f));
        }
        cp_wait_all();                 // this layer's image landed
        __syncthreads();               // everyone done with the old buffer
        if (L == 1)                    // prefetch L2 image into buf0 during L1 MMA
            cp_img(smem + SM_BUF0, wimg0 + 2, tid);
        #pragma unroll
        for (int j = 0; j < 64; ++j) acc[j] = 0.f;
        const char* bb = smem + (L == 1 ? SM_BUF1 : SM_BUF0);
        #pragma unroll
        for (int s = 0; s < 8; ++s)
            mma_step(acc, &Ahi[s * 4], bb + (s * 16) * 256 + (lane << 3));
    }

    // ---- final: bias + LayerNorm + residual (+ scatter) ----
    {
        const float* bias = (const float*)(smem + SM_B2);
        float sl = 0.f, ssl = 0.f, sh2 = 0.f, ssh = 0.f;
        #pragma unroll
        for (int t = 0; t < 16; ++t) {
            float2 bz = *(const float2*)(bias + t * 8 + q * 2);
            float v0 = acc[t * 4 + 0] + bz.x, v1 = acc[t * 4 + 1] + bz.y;
            float v2 = acc[t * 4 + 2] + bz.x, v3 = acc[t * 4 + 3] + bz.y;
            acc[t * 4 + 0] = v0; acc[t * 4 + 1] = v1;
            acc[t * 4 + 2] = v2; acc[t * 4 + 3] = v3;
            sl  += v0 + v1; ssl = fmaf(v0, v0, fmaf(v1, v1, ssl));
            sh2 += v2 + v3; ssh = fmaf(v2, v2, fmaf(v3, v3, ssh));
        }
        #pragma unroll
        for (int o = 1; o <= 2; o <<= 1) {
            sl  += __shfl_xor_sync(0xffffffffu, sl,  o);
            ssl += __shfl_xor_sync(0xffffffffu, ssl, o);
            sh2 += __shfl_xor_sync(0xffffffffu, sh2, o);
            ssh += __shfl_xor_sync(0xffffffffu, ssh, o);
        }
        const float mul = sl  * (1.f / 128.f);
        const float muh = sh2 * (1.f / 128.f);
        const float rsl = rsqrtf(ssl * (1.f / 128.f) - mul * mul + 1e-5f);
        const float rsh = rsqrtf(ssh * (1.f / 128.f) - muh * muh + 1e-5f);

        int rvl = 0, rvh = 0;
        if (IS_EDGE) { rvl = receivers[gl]; rvh = receivers[gh]; }
        const float* gw = (const float*)(smem + SM_G);
        const float* bw = (const float*)(smem + SM_BE);

        #pragma unroll
        for (int t = 0; t < 16; ++t) {
            const int col = t * 8 + q * 2;
            float2 gg = *(const float2*)(gw + col);
            float2 bb = *(const float2*)(bw + col);
            if (gel < M) {
                float ne0 = fmaf(gg.x, (acc[t * 4 + 0] - mul) * rsl, bb.x);
                float ne1 = fmaf(gg.y, (acc[t * 4 + 1] - mul) * rsl, bb.y);
                float2 rf = *(const float2*)(resid + (size_t)gel * 128 + col);
                *(float2*)(out + (size_t)gel * 128 + col) = make_float2(ne0 + rf.x, ne1 + rf.y);
                if (IS_EDGE)
                    atomicAdd((float2*)&g_seg[(size_t)rvl * 128 + col], make_float2(ne0, ne1));
            }
            if (geh < M) {
                float ne2 = fmaf(gg.x, (acc[t * 4 + 2] - muh) * rsh, bb.x);
                float ne3 = fmaf(gg.y, (acc[t * 4 + 3] - muh) * rsh, bb.y);
                float2 rf = *(const float2*)(resid + (size_t)geh * 128 + col);
                *(float2*)(out + (size_t)geh * 128 + col) = make_float2(ne2 + rf.x, ne3 + rf.y);
                if (IS_EDGE)
                    atomicAdd((float2*)&g_seg[(size_t)rvh * 128 + col], make_float2(ne2, ne3));
            }
        }
    }
}

// ---------------- launch ----------------
extern "C" void kernel_launch(void* const* d_in, const int* in_sizes, int n_in,
                              void* d_out, int out_size)
{
    const float* nodef     = (const float*)d_in[0];
    const float* edgef     = (const float*)d_in[1];
    const int*   senders   = (const int*)d_in[2];
    const int*   receivers = (const int*)d_in[3];
    const float* eW0 = (const float*)d_in[4];  const float* eb0 = (const float*)d_in[5];
    const float* eW1 = (const float*)d_in[6];  const float* eb1 = (const float*)d_in[7];
    const float* eW2 = (const float*)d_in[8];  const float* eb2 = (const float*)d_in[9];
    const float* eg  = (const float*)d_in[10]; const float* ebt = (const float*)d_in[11];
    const float* nW0 = (const float*)d_in[12]; const float* nb0 = (const float*)d_in[13];
    const float* nW1 = (const float*)d_in[14]; const float* nb1 = (const float*)d_in[15];
    const float* nW2 = (const float*)d_in[16]; const float* nb2 = (const float*)d_in[17];
    const float* ng  = (const float*)d_in[18]; const float* nbt = (const float*)d_in[19];

    const int N = in_sizes[0] / 128;
    const int E = in_sizes[2];
    float* out_node = (float*)d_out;
    float* out_edge = out_node + (size_t)N * 128;

    cudaFuncSetAttribute(precomp_kernel,
                         cudaFuncAttributeMaxDynamicSharedMemorySize, SMEM_PRE);
    cudaFuncSetAttribute(gnn5<true>,
                         cudaFuncAttributeMaxDynamicSharedMemorySize, SMEM_TOTAL);
    cudaFuncSetAttribute(gnn5<false>,
                         cudaFuncAttributeMaxDynamicSharedMemorySize, SMEM_TOTAL);

    // weight images: 0=eW0s 1=eW0r 2=eW0e 3=eW1 4=eW2 5=nW0a 6=nW0b 7=nW1 8=nW2
    prep_all_kernel<<<(1152 * 128 + 255) / 256, 256>>>(eW0, eW1, eW2, nW0, nW1, nW2);
    zero_seg_kernel<<<(N * 32 + 255) / 256, 256>>>(N * 32);

    const int ntile_n = (N + 127) / 128;

    // H0s / H0r / H0n precompute over nodes (fp16 outputs)
    precomp_kernel<<<296, NT, SMEM_PRE>>>(nodef, N, ntile_n, 0, 1, 5);

    // edge pass (128-row tiles)
    gnn5<true><<<(E + 127) / 128, NT, SMEM_TOTAL>>>(
        edgef, senders, receivers,
        eb0, eb1, eb2, eg, ebt, edgef, out_edge, E, 2);

    // node pass (128-row tiles)
    gnn5<false><<<ntile_n, NT, SMEM_TOTAL>>>(
        nullptr, nullptr, nullptr,
        nb0, nb1, nb2, ng, nbt, nodef, out_node, N, 6);
}

// round 17
// speedup vs baseline: 1.1380x; 1.0481x over previous
#include <cuda_runtime.h>
#include <cuda_fp16.h>
#include <cstdint>

#define NT 256

// ---------------- global scratch ----------------
static __device__ float   g_seg[(size_t)50176 * 128];
static __device__ __half  g_h0s[(size_t)50176 * 128];
static __device__ __half  g_h0r[(size_t)50176 * 128];
static __device__ __half  g_h0n[(size_t)50176 * 128];
static __device__ __half  g_wh[9 * 16384];

// ---------------- helpers ----------------
__device__ __forceinline__ uint32_t cvt2(float2 v) {
    __half2 h = __floats2half2_rn(v.x, v.y);
    return *reinterpret_cast<const uint32_t*>(&h);
}
__device__ __forceinline__ uint32_t cvt2f(float x, float y) { return cvt2(make_float2(x, y)); }
__device__ __forceinline__ float2 h2f(uint32_t u) {
    __half2 h = *reinterpret_cast<const __half2*>(&u);
    return __half22float2(h);
}
__device__ __forceinline__ void mma4(float* c, const uint32_t* a, uint2 b) {
    asm("mma.sync.aligned.m16n8k16.row.col.f32.f16.f16.f32 "
        "{%0,%1,%2,%3}, {%4,%5,%6,%7}, {%8,%9}, {%0,%1,%2,%3};"
        : "+f"(c[0]), "+f"(c[1]), "+f"(c[2]), "+f"(c[3])
        : "r"(a[0]), "r"(a[1]), "r"(a[2]), "r"(a[3]), "r"(b.x), "r"(b.y));
}
// precomp-only 16-row step
__device__ __forceinline__ void mma_step(float* acc, const uint32_t* ah, const char* bbase) {
    #pragma unroll
    for (int t = 0; t < 16; ++t) {
        uint2 wh = *(const uint2*)(bbase + t * 256);
        mma4(&acc[t * 4], ah, wh);
    }
}

// ---------------- async copy of one 32KB weight image ----------------
__device__ __forceinline__ void cp_img(void* smem_dst, int img, int tid) {
    uint32_t d = (uint32_t)__cvta_generic_to_shared(smem_dst);
    const uint4* src = (const uint4*)(g_wh + (size_t)img * 16384);
    #pragma unroll
    for (int i = tid; i < 2048; i += NT)
        asm volatile("cp.async.ca.shared.global [%0], [%1], 16;"
                     :: "r"(d + i * 16), "l"(src + i));
    asm volatile("cp.async.commit_group;" ::: "memory");
}
__device__ __forceinline__ void cp_wait_all() {
    asm volatile("cp.async.wait_group 0;" ::: "memory");
}

// ---------------- coalesced staging into block act buffer (stride 68 u32/row) ----------------
__device__ __forceinline__ void stage_h0_edge(uint32_t* stg, const int* idx0, const int* idx1,
                                              int rowbase, int M, int lane) {
    #pragma unroll 4
    for (int lr = 0; lr < 16; ++lr) {
        int rc = min(rowbase + lr, M - 1);
        const uint32_t* ps = (const uint32_t*)(g_h0s + (size_t)idx0[rc] * 128);
        const uint32_t* pr = (const uint32_t*)(g_h0r + (size_t)idx1[rc] * 128);
        uint2 va = *(const uint2*)(ps + lane * 2);
        uint2 vb = *(const uint2*)(pr + lane * 2);
        __half2 s0 = __hadd2(*(__half2*)&va.x, *(__half2*)&vb.x);
        __half2 s1 = __hadd2(*(__half2*)&va.y, *(__half2*)&vb.y);
        stg[lr * 68 + lane * 2]     = *(uint32_t*)&s0;
        stg[lr * 68 + lane * 2 + 1] = *(uint32_t*)&s1;
    }
}
__device__ __forceinline__ void stage_h0_node(uint32_t* stg, int rowbase, int Nn, int lane) {
    #pragma unroll 4
    for (int lr = 0; lr < 16; ++lr) {
        int rc = min(rowbase + lr, Nn - 1);
        const uint32_t* p = (const uint32_t*)(g_h0n + (size_t)rc * 128);
        uint2 v = *(const uint2*)(p + lane * 2);
        stg[lr * 68 + lane * 2]     = v.x;
        stg[lr * 68 + lane * 2 + 1] = v.y;
    }
}
__device__ __forceinline__ void stage_f32(uint32_t* stg, const float* src,
                                          int rowbase, int M, int lane) {
    #pragma unroll 4
    for (int lr = 0; lr < 16; ++lr) {
        int rc = min(rowbase + lr, M - 1);
        const float2* p = (const float2*)(src + (size_t)rc * 128);
        stg[lr * 68 + lane]      = cvt2(p[lane]);
        stg[lr * 68 + lane + 32] = cvt2(p[lane + 32]);
    }
}

// ---------------- prep kernels ----------------
__global__ void zero_seg_kernel(int n4) {
    int i = blockIdx.x * blockDim.x + threadIdx.x;
    if (i < n4) reinterpret_cast<float4*>(g_seg)[i] = make_float4(0.f, 0.f, 0.f, 0.f);
}
__global__ void prep_all_kernel(const float* __restrict__ eW0, const float* __restrict__ eW1,
                                const float* __restrict__ eW2, const float* __restrict__ nW0,
                                const float* __restrict__ nW1, const float* __restrict__ nW2) {
    int t = blockIdx.x * blockDim.x + threadIdx.x;
    if (t >= 1152 * 128) return;
    int kg = t >> 7, n = t & 127;
    const float* W; int k, baseImg;
    if      (kg < 384)  { W = eW0; k = kg;        baseImg = 0; }
    else if (kg < 512)  { W = eW1; k = kg - 384;  baseImg = 3; }
    else if (kg < 640)  { W = eW2; k = kg - 512;  baseImg = 4; }
    else if (kg < 896)  { W = nW0; k = kg - 640;  baseImg = 5; }
    else if (kg < 1024) { W = nW1; k = kg - 896;  baseImg = 7; }
    else                { W = nW2; k = kg - 1024; baseImg = 8; }
    float x = W[k * 128 + n];
    int chunk = k >> 7, kc = k & 127;
    int kstep = kc >> 4, kk = kc & 15;
    int reg = kk >> 3, kb = kk & 7;
    int lane = (n & 7) * 4 + (kb >> 1), cb = kb & 1;
    int frag = kstep * 16 + (n >> 3);
    size_t di = (size_t)(baseImg + chunk) * 16384 + (size_t)frag * 128 + lane * 4 + reg * 2 + cb;
    g_wh[di] = __float2half_rn(x);
}

// ---------------- SMEM map (bytes) ----------------
#define SM_BUF0 0
#define SM_BUF1 32768
#define SM_ACT  65536       // 128 rows x 272B = 34816
#define SM_RS   100352      // 128 rows x 2 halves x float2 = 2048
#define SM_B0   102400
#define SM_B1   102912
#define SM_B2   103424
#define SM_G    103936
#define SM_BE   104448
#define SMEM_TOTAL 104960
#define SMEM_PRE   32768

// ---------------- precompute (unchanged core) ----------------
__global__ __launch_bounds__(NT, 2)
void precomp_kernel(const float* __restrict__ nodef, int Nn, int ntiles,
                    int i0, int i1, int i2)
{
    extern __shared__ char smem[];
    const int tid = threadIdx.x, wid = tid >> 5, lane = tid & 31, q = lane & 3;
    const int rl = wid * 16 + (lane >> 2);
    const int imgs[3] = {i0, i1, i2};
    __half* const outs[3] = {g_h0s, g_h0r, g_h0n};

    for (int j = 0; j < 3; ++j) {
        __syncthreads();
        cp_img(smem, imgs[j], tid);
        cp_wait_all();
        __syncthreads();
        for (int tile = blockIdx.x; tile < ntiles; tile += gridDim.x) {
            const int gel = tile * 128 + rl, geh = gel + 8;
            const int gl = min(gel, Nn - 1), gh = min(geh, Nn - 1);
            const float* pl = nodef + (size_t)gl * 128;
            const float* ph = nodef + (size_t)gh * 128;
            float acc[64];
            #pragma unroll
            for (int i = 0; i < 64; ++i) acc[i] = 0.f;
            #pragma unroll
            for (int s = 0; s < 8; ++s) {
                const int k0 = s * 16 + q * 2;
                uint32_t ahf[4];
                ahf[0] = cvt2(*(const float2*)(pl + k0));
                ahf[1] = cvt2(*(const float2*)(ph + k0));
                ahf[2] = cvt2(*(const float2*)(pl + k0 + 8));
                ahf[3] = cvt2(*(const float2*)(ph + k0 + 8));
                mma_step(acc, ahf, smem + (s * 16) * 256 + (lane << 3));
            }
            __half* o = outs[j];
            #pragma unroll
            for (int t = 0; t < 16; ++t) {
                const int col = t * 8 + q * 2;
                if (gel < Nn)
                    *(uint32_t*)(o + (size_t)gel * 128 + col) = cvt2f(acc[t * 4 + 0], acc[t * 4 + 1]);
                if (geh < Nn)
                    *(uint32_t*)(o + (size_t)geh * 128 + col) = cvt2f(acc[t * 4 + 2], acc[t * 4 + 3]);
            }
        }
    }
}

// ---------------- main kernel: M=32 rows, N=64 cols per warp ----------------
// Warps w and w+4 share rows ((w&3)*32..+32); col half c = w>>2.
template<bool IS_EDGE>
__global__ __launch_bounds__(NT, 2)
void gnn6(const float* __restrict__ chunkA_in,
          const int*   __restrict__ senders,
          const int*   __restrict__ receivers,
          const float* __restrict__ b0, const float* __restrict__ b1,
          const float* __restrict__ b2,
          const float* __restrict__ gma, const float* __restrict__ bta,
          const float* __restrict__ resid,
          float* __restrict__ out, int M, int wimg0)
{
    extern __shared__ char smem[];
    const int tid = threadIdx.x, wid = tid >> 5, lane = tid & 31, q = lane & 3;
    const int lr = lane >> 2;
    const int c = wid >> 2;             // col half (0/1)
    const int R = (wid & 3) * 32;       // row base within tile
    const int r0 = blockIdx.x * 128;
    uint32_t* act = (uint32_t*)(smem + SM_ACT);

    // prologue
    cp_img(smem + SM_BUF0, wimg0, tid);
    for (int i = tid; i < 128; i += NT) {
        ((float*)(smem + SM_B0))[i] = b0[i];
        ((float*)(smem + SM_B1))[i] = b1[i];
        ((float*)(smem + SM_B2))[i] = b2[i];
        ((float*)(smem + SM_G ))[i] = gma[i];
        ((float*)(smem + SM_BE))[i] = bta[i];
    }

    const int rowbase_stage = r0 + wid * 16;
    // rows per thread: i = g*2 + h -> R + g*16 + lr + h*8
    int rloc[4], grow[4], gcl[4];
    #pragma unroll
    for (int i = 0; i < 4; ++i) {
        rloc[i] = R + (i >> 1) * 16 + lr + (i & 1) * 8;
        grow[i] = r0 + rloc[i];
        gcl[i] = min(grow[i], M - 1);
    }

    // ---- stage h0 (block-wide) ----
    if (IS_EDGE) stage_h0_edge(act + wid * 1088, senders, receivers, rowbase_stage, M, lane);
    else         stage_h0_node(act + wid * 1088, rowbase_stage, M, lane);
    __syncthreads();                                   // S1

    // ---- acc init: own 32 rows x own 64 cols ----
    float acc[64];
    #pragma unroll
    for (int g = 0; g < 2; ++g) {
        const int base = (R + g * 16 + lr) * 68 + c * 32 + q;
        #pragma unroll
        for (int t = 0; t < 8; ++t) {
            float2 f0 = h2f(act[base + t * 4]);
            float2 f1 = h2f(act[base + 544 + t * 4]);
            acc[(g * 8 + t) * 4 + 0] = f0.x; acc[(g * 8 + t) * 4 + 1] = f0.y;
            acc[(g * 8 + t) * 4 + 2] = f1.x; acc[(g * 8 + t) * 4 + 3] = f1.y;
        }
    }
    __syncthreads();                                   // S2

    // ---- stage L0 source (fp32 -> fp16) ----
    stage_f32(act + wid * 1088, IS_EDGE ? chunkA_in : g_seg, rowbase_stage, M, lane);
    cp_wait_all();
    __syncthreads();                                   // S3
    cp_img(smem + SM_BUF1, wimg0 + 1, tid);

    // ---- layer 0 MMA: A from act buffer (full K), B half from BUF0 ----
    #pragma unroll
    for (int s = 0; s < 8; ++s) {
        uint32_t a0[4], a1[4];
        const int b0i = (R + lr) * 68 + s * 8 + q;
        a0[0] = act[b0i];        a0[1] = act[b0i + 544];
        a0[2] = act[b0i + 4];    a0[3] = act[b0i + 548];
        const int b1i = b0i + 16 * 68;
        a1[0] = act[b1i];        a1[1] = act[b1i + 544];
        a1[2] = act[b1i + 4];    a1[3] = act[b1i + 548];
        const char* bb = smem + SM_BUF0 + (s * 16 + c * 8) * 256 + (lane << 3);
        #pragma unroll
        for (int t = 0; t < 8; ++t) {
            uint2 wh = *(const uint2*)(bb + t * 256);
            mma4(&acc[(0 * 8 + t) * 4], a0, wh);
            mma4(&acc[(1 * 8 + t) * 4], a1, wh);
        }
    }

    // ---- layers 1, 2 ----
    uint32_t Ahi[32];
    const int cp = 1 - c;
    #pragma unroll
    for (int L = 1; L <= 2; ++L) {
        const float* bias = (const float*)(smem + (L == 1 ? SM_B0 : SM_B1));
        #pragma unroll
        for (int g = 0; g < 2; ++g)
            #pragma unroll
            for (int t = 0; t < 8; ++t) {
                float2 bz = *(const float2*)(bias + c * 64 + t * 8 + q * 2);
                Ahi[(g * 8 + t) * 2 + 0] = cvt2f(fmaxf(acc[(g * 8 + t) * 4 + 0] + bz.x, 0.f),
                                                 fmaxf(acc[(g * 8 + t) * 4 + 1] + bz.y, 0.f));
                Ahi[(g * 8 + t) * 2 + 1] = cvt2f(fmaxf(acc[(g * 8 + t) * 4 + 2] + bz.x, 0.f),
                                                 fmaxf(acc[(g * 8 + t) * 4 + 3] + bz.y, 0.f));
            }
        __syncthreads();                               // S4/S6: act reads done
        // store own half for partner
        #pragma unroll
        for (int g = 0; g < 2; ++g) {
            const int base = (R + g * 16 + lr) * 68 + c * 32 + q;
            #pragma unroll
            for (int t = 0; t < 8; ++t) {
                act[base + t * 4]       = Ahi[(g * 8 + t) * 2 + 0];
                act[base + 544 + t * 4] = Ahi[(g * 8 + t) * 2 + 1];
            }
        }
        cp_wait_all();
        __syncthreads();                               // S5/S7
        if (L == 1) cp_img(smem + SM_BUF0, wimg0 + 2, tid);
        #pragma unroll
        for (int j = 0; j < 64; ++j) acc[j] = 0.f;
        const char* bufp = smem + (L == 1 ? SM_BUF1 : SM_BUF0);
        #pragma unroll
        for (int s = 0; s < 8; ++s) {
            uint32_t a0[4], a1[4];
            if ((s >> 2) == c) {
                const int t0 = 2 * s - 8 * c;
                a0[0] = Ahi[(0 * 8 + t0) * 2 + 0]; a0[1] = Ahi[(0 * 8 + t0) * 2 + 1];
                a0[2] = Ahi[(0 * 8 + t0 + 1) * 2 + 0]; a0[3] = Ahi[(0 * 8 + t0 + 1) * 2 + 1];
                a1[0] = Ahi[(1 * 8 + t0) * 2 + 0]; a1[1] = Ahi[(1 * 8 + t0) * 2 + 1];
                a1[2] = Ahi[(1 * 8 + t0 + 1) * 2 + 0]; a1[3] = Ahi[(1 * 8 + t0 + 1) * 2 + 1];
            } else {
                const int b0i = (R + lr) * 68 + cp * 32 + (s - 4 * cp) * 8 + q;
                a0[0] = act[b0i];     a0[1] = act[b0i + 544];
                a0[2] = act[b0i + 4]; a0[3] = act[b0i + 548];
                const int b1i = b0i + 16 * 68;
                a1[0] = act[b1i];     a1[1] = act[b1i + 544];
                a1[2] = act[b1i + 4]; a1[3] = act[b1i + 548];
            }
            const char* bb = bufp + (s * 16 + c * 8) * 256 + (lane << 3);
            #pragma unroll
            for (int t = 0; t < 8; ++t) {
                uint2 wh = *(const uint2*)(bb + t * 256);
                mma4(&acc[(0 * 8 + t) * 4], a0, wh);
                mma4(&acc[(1 * 8 + t) * 4], a1, wh);
            }
        }
    }

    // ---- epilogue: bias + cross-warp LN + residual (+ scatter) ----
    {
        const float* bias = (const float*)(smem + SM_B2);
        float sm_[4] = {0.f, 0.f, 0.f, 0.f}, sq[4] = {0.f, 0.f, 0.f, 0.f};
        #pragma unroll
        for (int g = 0; g < 2; ++g)
            #pragma unroll
            for (int t = 0; t < 8; ++t) {
                float2 bz = *(const float2*)(bias + c * 64 + t * 8 + q * 2);
                float v0 = acc[(g * 8 + t) * 4 + 0] + bz.x;
                float v1 = acc[(g * 8 + t) * 4 + 1] + bz.y;
                float v2 = acc[(g * 8 + t) * 4 + 2] + bz.x;
                float v3 = acc[(g * 8 + t) * 4 + 3] + bz.y;
                acc[(g * 8 + t) * 4 + 0] = v0; acc[(g * 8 + t) * 4 + 1] = v1;
                acc[(g * 8 + t) * 4 + 2] = v2; acc[(g * 8 + t) * 4 + 3] = v3;
                sm_[g * 2 + 0] += v0 + v1; sq[g * 2 + 0] = fmaf(v0, v0, fmaf(v1, v1, sq[g * 2 + 0]));
                sm_[g * 2 + 1] += v2 + v3; sq[g * 2 + 1] = fmaf(v2, v2, fmaf(v3, v3, sq[g * 2 + 1]));
            }
        #pragma unroll
        for (int o = 1; o <= 2; o <<= 1)
            #pragma unroll
            for (int i = 0; i < 4; ++i) {
                sm_[i] += __shfl_xor_sync(0xffffffffu, sm_[i], o);
                sq[i]  += __shfl_xor_sync(0xffffffffu, sq[i],  o);
            }
        float2* rs = (float2*)(smem + SM_RS);
        if (q == 0) {
            #pragma unroll
            for (int i = 0; i < 4; ++i)
                rs[rloc[i] * 2 + c] = make_float2(sm_[i], sq[i]);
        }
        __syncthreads();                               // S8
        float mu[4], rstd[4];
        #pragma unroll
        for (int i = 0; i < 4; ++i) {
            float2 h0 = rs[rloc[i] * 2 + 0];
            float2 h1 = rs[rloc[i] * 2 + 1];
            float S = h0.x + h1.x, Q = h0.y + h1.y;
            mu[i] = S * (1.f / 128.f);
            rstd[i] = rsqrtf(Q * (1.f / 128.f) - mu[i] * mu[i] + 1e-5f);
        }
        int rv[4];
        if (IS_EDGE) {
            #pragma unroll
            for (int i = 0; i < 4; ++i) rv[i] = receivers[gcl[i]];
        }
        const float* gw = (const float*)(smem + SM_G);
        const float* bw = (const float*)(smem + SM_BE);
        #pragma unroll
        for (int g = 0; g < 2; ++g)
            #pragma unroll
            for (int t = 0; t < 8; ++t) {
                const int col = c * 64 + t * 8 + q * 2;
                float2 gg = *(const float2*)(gw + col);
                float2 bb = *(const float2*)(bw + col);
                #pragma unroll
                for (int h = 0; h < 2; ++h) {
                    const int i = g * 2 + h;
                    if (grow[i] < M) {
                        float ne0 = fmaf(gg.x, (acc[(g * 8 + t) * 4 + h * 2 + 0] - mu[i]) * rstd[i], bb.x);
                        float ne1 = fmaf(gg.y, (acc[(g * 8 + t) * 4 + h * 2 + 1] - mu[i]) * rstd[i], bb.y);
                        float2 rf = *(const float2*)(resid + (size_t)grow[i] * 128 + col);
                        *(float2*)(out + (size_t)grow[i] * 128 + col) = make_float2(ne0 + rf.x, ne1 + rf.y);
                        if (IS_EDGE)
                            atomicAdd((float2*)&g_seg[(size_t)rv[i] * 128 + col], make_float2(ne0, ne1));
                    }
                }
            }
    }
}

// ---------------- launch ----------------
extern "C" void kernel_launch(void* const* d_in, const int* in_sizes, int n_in,
                              void* d_out, int out_size)
{
    const float* nodef     = (const float*)d_in[0];
    const float* edgef     = (const float*)d_in[1];
    const int*   senders   = (const int*)d_in[2];
    const int*   receivers = (const int*)d_in[3];
    const float* eW0 = (const float*)d_in[4];  const float* eb0 = (const float*)d_in[5];
    const float* eW1 = (const float*)d_in[6];  const float* eb1 = (const float*)d_in[7];
    const float* eW2 = (const float*)d_in[8];  const float* eb2 = (const float*)d_in[9];
    const float* eg  = (const float*)d_in[10]; const float* ebt = (const float*)d_in[11];
    const float* nW0 = (const float*)d_in[12]; const float* nb0 = (const float*)d_in[13];
    const float* nW1 = (const float*)d_in[14]; const float* nb1 = (const float*)d_in[15];
    const float* nW2 = (const float*)d_in[16]; const float* nb2 = (const float*)d_in[17];
    const float* ng  = (const float*)d_in[18]; const float* nbt = (const float*)d_in[19];

    const int N = in_sizes[0] / 128;
    const int E = in_sizes[2];
    float* out_node = (float*)d_out;
    float* out_edge = out_node + (size_t)N * 128;

    cudaFuncSetAttribute(precomp_kernel,
                         cudaFuncAttributeMaxDynamicSharedMemorySize, SMEM_PRE);
    cudaFuncSetAttribute(gnn6<true>,
                         cudaFuncAttributeMaxDynamicSharedMemorySize, SMEM_TOTAL);
    cudaFuncSetAttribute(gnn6<false>,
                         cudaFuncAttributeMaxDynamicSharedMemorySize, SMEM_TOTAL);

    // weight images: 0=eW0s 1=eW0r 2=eW0e 3=eW1 4=eW2 5=nW0a 6=nW0b 7=nW1 8=nW2
    prep_all_kernel<<<(1152 * 128 + 255) / 256, 256>>>(eW0, eW1, eW2, nW0, nW1, nW2);
    zero_seg_kernel<<<(N * 32 + 255) / 256, 256>>>(N * 32);

    const int ntile_n = (N + 127) / 128;

    precomp_kernel<<<296, NT, SMEM_PRE>>>(nodef, N, ntile_n, 0, 1, 5);

    gnn6<true><<<(E + 127) / 128, NT, SMEM_TOTAL>>>(
        edgef, senders, receivers,
        eb0, eb1, eb2, eg, ebt, edgef, out_edge, E, 2);

    gnn6<false><<<ntile_n, NT, SMEM_TOTAL>>>(
        nullptr, nullptr, nullptr,
        nb0, nb1, nb2, ng, nbt, nodef, out_node, N, 6);
}